// round 7
// baseline (speedup 1.0000x reference)
#include <cuda_runtime.h>

// SobelLoss: loss = sum_{voxels,d in {x,y,z}} |conv_d(moved - label)| / (3*N)
// Shapes: (B=2, 1, D=160, H=192, W=160) fp32, zero padding.
// Sobel separable: S=[1,2,1] smooth, D=[-1,0,1] derivative.
// This version: packed f32x2 math over (even,odd) output-row pairs,
// row-pair-interleaved smem planes, LDS.64 stencil reads, single kernel
// (last CTA finalizes the scalar output).

typedef unsigned long long ull;

#define DIMX 160
#define DIMY 192
#define DIMZ 160
#define NBATCH 2
#define PLANE (DIMY * DIMX)

#define TX 32
#define TY 8
#define NT (TX * TY)            // 256
#define OY 16                   // output rows per block (2 per thread)
#define ZCHUNK 16
#define NZCH (DIMZ / ZCHUNK)    // 10

#define TILE_W 40               // raw tile cols (gx in [32bx-4, 32bx+35])
#define NPAIR 9                 // 18 raw rows as 9 (even,odd) pairs
#define PLANE_ULL (NPAIR * TILE_W)   // 360 ull per plane buffer
#define NSLOT 180               // fetch slots: 9 pairs x 20 col-pairs
#define NBUF 3

#define GRID_X (DIMX / TX)      // 5
#define GRID_Y (DIMY / OY)      // 12
#define TOTAL_CTAS (GRID_X * GRID_Y * NBATCH * NZCH)   // 1200

// 1 / (3 * B*D*H*W) = 1 / 29491200
#define SCALE 3.3908420632258286e-08f

__device__ float    g_acc = 0.0f;
__device__ unsigned g_cnt = 0;

// ---- packed f32x2 helpers (Blackwell sm_103a) ----
__device__ __forceinline__ ull pk(float lo, float hi) {
    ull r; asm("mov.b64 %0, {%1, %2};" : "=l"(r) : "f"(lo), "f"(hi)); return r;
}
__device__ __forceinline__ void upk(ull p, float& lo, float& hi) {
    asm("mov.b64 {%0, %1}, %2;" : "=f"(lo), "=f"(hi) : "l"(p));
}
__device__ __forceinline__ ull padd(ull a, ull b) {
    ull r; asm("add.rn.f32x2 %0, %1, %2;" : "=l"(r) : "l"(a), "l"(b)); return r;
}
__device__ __forceinline__ ull pfma(ull a, ull b, ull c) {   // a*b + c
    ull r; asm("fma.rn.f32x2 %0, %1, %2, %3;" : "=l"(r) : "l"(a), "l"(b), "l"(c)); return r;
}
// (hi(a), lo(b))
__device__ __forceinline__ ull pmid(ull a, ull b) {
    float alo, ahi, blo, bhi;
    upk(a, alo, ahi); upk(b, blo, bhi);
    return pk(ahi, blo);
}

__launch_bounds__(NT, 8)   // 8 CTAs/SM -> 1200-CTA grid fits in ONE wave
__global__ void sobel_loss_kernel(const float* __restrict__ moved,
                                  const float* __restrict__ label,
                                  float* __restrict__ out)
{
    // plane buffer: [pair][col] = float2{ raw row 2*pair, raw row 2*pair+1 }
    __shared__ ull tile2[NBUF][PLANE_ULL];

    const int tx  = threadIdx.x;
    const int ty  = threadIdx.y;
    const int tid = ty * TX + tx;

    const int b  = blockIdx.z / NZCH;
    const int z0 = (blockIdx.z % NZCH) * ZCHUNK;

    const int gy0  = blockIdx.y * OY - 1;     // global y of tile row 0
    const int gxv0 = blockIdx.x * TX - 4;     // global x of tile col 0 (8B aligned)

    const float* mb = moved + (size_t)b * DIMZ * PLANE;
    const float* lb = label + (size_t)b * DIMZ * PLANE;

    const ull C2  = pk(2.0f, 2.0f);
    const ull CM1 = pk(-1.0f, -1.0f);

    // ---- fetch slot: (pair, col-pair) -> 2 rows x 2 cols per thread ----
    const int pair = tid / 20;                // 0..8 (tid < 180)
    const int vc2  = tid - pair * 20;         // 0..19
    const int gx   = gxv0 + 2 * vc2;          // even, 8B aligned
    const int gyE  = gy0 + 2 * pair;
    const bool slotok = (tid < NSLOT) && ((unsigned)gx < (unsigned)DIMX);
    const int offE = (slotok && (unsigned)gyE       < (unsigned)DIMY) ? (gyE * DIMX + gx)       : -1;
    const int offO = (slotok && (unsigned)(gyE + 1) < (unsigned)DIMY) ? ((gyE + 1) * DIMX + gx) : -1;
    const int wOff = pair * TILE_W + 2 * vc2;  // ull index; 16B aligned

    ull pre0, pre1;   // prefetched: (colL: even,odd rows), (colR: even,odd rows)

    auto fetch = [&](int z) {
        ull mE = 0, lE = 0, mO = 0, lO = 0;
        if ((unsigned)z < (unsigned)DIMZ) {
            const float* mz = mb + (size_t)z * PLANE;
            const float* lz = lb + (size_t)z * PLANE;
            if (offE >= 0) { mE = *(const ull*)(mz + offE); lE = *(const ull*)(lz + offE); }
            if (offO >= 0) { mO = *(const ull*)(mz + offO); lO = *(const ull*)(lz + offO); }
        }
        ull vE = pfma(lE, CM1, mE);   // moved - label, even row (2 cols)
        ull vO = pfma(lO, CM1, mO);   // odd row
        float e0, e1, o0, o1;
        upk(vE, e0, e1); upk(vO, o0, o1);
        pre0 = pk(e0, o0);            // column L: (even,odd)
        pre1 = pk(e1, o1);            // column R: (even,odd)
    };

    auto store = [&](int buf) {
        if (tid < NSLOT)
            *(ulonglong2*)&tile2[buf][wOff] = make_ulonglong2(pre0, pre1);
    };

    // ---- packed in-plane partials for this thread's output-row pair ----
    // raw rows 2ty..2ty+3 = pairs ty, ty+1. Output rows: tile 2ty+1 (A), 2ty+2 (B).
    //   s = x(-1)+2x(0)+x(+1), d = x(+1)-x(-1) per raw row (packed 2 rows/op)
    //   qP = (qA,qB) = sP1 - sP0          (perfect pair alignment)
    //   rP = sP0 + 2*mid(sP0,sP1) + sP1
    //   pP = dP0 + 2*mid(dP0,dP1) + dP1
    auto compute_pqr = [&](int buf, ull& pP, ull& qP, ull& rP) {
        const ull* b0 = &tile2[buf][ty * TILE_W + tx + 3];
        ull a0 = b0[0],          c0 = b0[1],          e0 = b0[2];
        ull a1 = b0[TILE_W],     c1 = b0[TILE_W + 1], e1 = b0[TILE_W + 2];
        ull s0 = padd(pfma(c0, C2, a0), e0);
        ull d0 = pfma(a0, CM1, e0);
        ull s1 = padd(pfma(c1, C2, a1), e1);
        ull d1 = pfma(a1, CM1, e1);
        qP = pfma(s0, CM1, s1);
        rP = padd(pfma(pmid(s0, s1), C2, s0), s1);
        pP = padd(pfma(pmid(d0, d1), C2, d0), d1);
    };

    // ---- prologue: planes z0-1, z0, z0+1 into buffers (plane p -> buf p%3) ----
    fetch(z0 - 1); store((z0 + 2) % NBUF);
    fetch(z0);     store(z0 % NBUF);
    fetch(z0 + 1); store((z0 + 1) % NBUF);
    __syncthreads();

    ull pP0, qP0, rP0, pP1, qP1, rP1;
    compute_pqr((z0 + 2) % NBUF, pP0, qP0, rP0);   // plane z0-1
    compute_pqr(z0 % NBUF,       pP1, qP1, rP1);   // plane z0

    fetch(z0 + 2);   // at loop iter k, prefetch regs hold plane z0+k+1

    float acc = 0.0f;
    int cBuf = (z0 + 1) % NBUF;   // buffer of compute plane z = z0+k
    int sBuf = (z0 + 2) % NBUF;   // store target for plane z+1

    #pragma unroll 4
    for (int k = 1; k <= ZCHUNK; ++k) {
        __syncthreads();                     // all compute(z-1) done everywhere
        if (k < ZCHUNK) {
            store(sBuf);                     // plane z+1 over plane z-2 (>=2 syncs back)
            if (k <= ZCHUNK - 2) fetch(z0 + k + 2);
        }

        ull pP2, qP2, rP2;
        compute_pqr(cBuf, pP2, qP2, rP2);    // plane z

        ull Gx = padd(pfma(pP1, C2, pP0), pP2);
        ull Gy = padd(pfma(qP1, C2, qP0), qP2);
        ull Gz = pfma(rP0, CM1, rP2);

        float gxa, gxb, gya, gyb, gza, gzb;
        upk(Gx, gxa, gxb); upk(Gy, gya, gyb); upk(Gz, gza, gzb);
        acc += fabsf(gxa) + fabsf(gya);
        acc += fabsf(gza) + fabsf(gxb);
        acc += fabsf(gyb) + fabsf(gzb);

        pP0 = pP1; pP1 = pP2;
        qP0 = qP1; qP1 = qP2;
        rP0 = rP1; rP1 = rP2;
        cBuf = (cBuf == NBUF - 1) ? 0 : cBuf + 1;
        sBuf = (sBuf == NBUF - 1) ? 0 : sBuf + 1;
    }

    // ---- block reduction ----
    #pragma unroll
    for (int o = 16; o > 0; o >>= 1)
        acc += __shfl_down_sync(0xFFFFFFFFu, acc, o);

    __shared__ float wsum[NT / 32];
    if ((tid & 31) == 0) wsum[tid >> 5] = acc;
    __syncthreads();

    if (tid < (NT / 32)) {
        float v = wsum[tid];
        #pragma unroll
        for (int o = (NT / 64); o > 0; o >>= 1)
            v += __shfl_down_sync(0xFFu, v, o);
        if (tid == 0) {
            atomicAdd(&g_acc, v);
            __threadfence();
            if (atomicAdd(&g_cnt, 1u) == TOTAL_CTAS - 1) {
                __threadfence();
                *out = g_acc * SCALE;
                g_acc = 0.0f;      // reset for next (graph-replayed) launch
                g_cnt = 0;
            }
        }
    }
}

extern "C" void kernel_launch(void* const* d_in, const int* in_sizes, int n_in,
                              void* d_out, int out_size)
{
    const float* moved = (const float*)d_in[0];
    const float* label = (const float*)d_in[1];
    float* out = (float*)d_out;

    dim3 grid(GRID_X, GRID_Y, NBATCH * NZCH);   // (5, 12, 20) = 1200 CTAs
    dim3 block(TX, TY);                         // (32, 8)
    sobel_loss_kernel<<<grid, block>>>(moved, label, out);
}

// round 8
// speedup vs baseline: 1.0735x; 1.0735x over previous
#include <cuda_runtime.h>

// SobelLoss: loss = sum_{voxels,d in {x,y,z}} |conv_d(moved - label)| / (3*N)
// Shapes: (B=2, 1, D=160, H=192, W=160) fp32, zero padding.
// Sobel separable: S=[1,2,1] smooth, D=[-1,0,1] derivative.
// This version: ZCHUNK=32 (600 CTAs, 4/SM, 64 regs), 4 smem buffers,
// TWO-plane-deep register prefetch (A/B sets, manual 2x unroll),
// 36-wide 8B-aligned tile, packed f32x2 math on (even,odd) row pairs.

typedef unsigned long long ull;

#define DIMX 160
#define DIMY 192
#define DIMZ 160
#define NBATCH 2
#define PLANE (DIMY * DIMX)

#define TX 32
#define TY 8
#define NT (TX * TY)            // 256
#define OY 16                   // output rows per block (2 per thread)
#define ZCHUNK 32
#define NZCH (DIMZ / ZCHUNK)    // 5

#define TILE_W 36               // raw cols: gx in [32bx-2, 32bx+33] (8B aligned)
#define NPAIR 9                 // 18 raw rows as 9 (even,odd) pairs
#define PLANE_ULL (NPAIR * TILE_W)     // 324 ull per plane buffer
#define NSLOT (NPAIR * (TILE_W / 2))   // 162 fetch slots (col pairs)
#define NBUF 4

#define GRID_X (DIMX / TX)      // 5
#define GRID_Y (DIMY / OY)      // 12
#define TOTAL_CTAS (GRID_X * GRID_Y * NBATCH * NZCH)   // 600

// 1 / (3 * B*D*H*W) = 1 / 29491200
#define SCALE 3.3908420632258286e-08f

__device__ float    g_acc = 0.0f;
__device__ unsigned g_cnt = 0;

// ---- packed f32x2 helpers (Blackwell sm_103a) ----
__device__ __forceinline__ ull pk(float lo, float hi) {
    ull r; asm("mov.b64 %0, {%1, %2};" : "=l"(r) : "f"(lo), "f"(hi)); return r;
}
__device__ __forceinline__ void upk(ull p, float& lo, float& hi) {
    asm("mov.b64 {%0, %1}, %2;" : "=f"(lo), "=f"(hi) : "l"(p));
}
__device__ __forceinline__ ull padd(ull a, ull b) {
    ull r; asm("add.rn.f32x2 %0, %1, %2;" : "=l"(r) : "l"(a), "l"(b)); return r;
}
__device__ __forceinline__ ull pfma(ull a, ull b, ull c) {   // a*b + c
    ull r; asm("fma.rn.f32x2 %0, %1, %2, %3;" : "=l"(r) : "l"(a), "l"(b), "l"(c)); return r;
}
// (hi(a), lo(b))
__device__ __forceinline__ ull pmid(ull a, ull b) {
    float alo, ahi, blo, bhi;
    upk(a, alo, ahi); upk(b, blo, bhi);
    return pk(ahi, blo);
}

__launch_bounds__(NT, 4)   // residency is grid-limited to ~4 CTAs/SM; allow 64 regs
__global__ void sobel_loss_kernel(const float* __restrict__ moved,
                                  const float* __restrict__ label,
                                  float* __restrict__ out)
{
    // plane buffer: [pair][col] = float2{ raw row 2*pair, raw row 2*pair+1 }
    __shared__ __align__(16) ull tile2[NBUF][PLANE_ULL];

    const int tx  = threadIdx.x;
    const int ty  = threadIdx.y;
    const int tid = ty * TX + tx;

    const int b  = blockIdx.z / NZCH;
    const int z0 = (blockIdx.z % NZCH) * ZCHUNK;

    const int gy0  = blockIdx.y * OY - 1;     // global y of tile row 0
    const int gxv0 = blockIdx.x * TX - 2;     // global x of tile col 0 (even -> 8B aligned)

    const float* mb = moved + (size_t)b * DIMZ * PLANE;
    const float* lb = label + (size_t)b * DIMZ * PLANE;

    const ull C2  = pk(2.0f, 2.0f);
    const ull CM1 = pk(-1.0f, -1.0f);

    // ---- fetch slot: (row pair, col pair) -> 2 rows x 2 cols per thread ----
    const int pair = tid / (TILE_W / 2);        // 0..8 (tid < 162)
    const int vc2  = tid - pair * (TILE_W / 2); // 0..17
    const int gx   = gxv0 + 2 * vc2;            // even, 8B aligned; pair fully in/out
    const int gyE  = gy0 + 2 * pair;
    const bool slotok = (tid < NSLOT) && ((unsigned)gx < (unsigned)DIMX);
    const int offE = (slotok && (unsigned)gyE       < (unsigned)DIMY) ? (gyE * DIMX + gx)       : -1;
    const int offO = (slotok && (unsigned)(gyE + 1) < (unsigned)DIMY) ? ((gyE + 1) * DIMX + gx) : -1;
    const int wOff = pair * TILE_W + 2 * vc2;   // ull index; 16B aligned (even)

    // two prefetch register sets (A/B) -> 2 planes in flight
    ull preA0, preA1, preB0, preB1;

    auto fetch = [&](int z, ull& p0, ull& p1) {
        ull mE = 0, lE = 0, mO = 0, lO = 0;
        if ((unsigned)z < (unsigned)DIMZ) {
            const float* mz = mb + (size_t)z * PLANE;
            const float* lz = lb + (size_t)z * PLANE;
            if (offE >= 0) { mE = *(const ull*)(mz + offE); lE = *(const ull*)(lz + offE); }
            if (offO >= 0) { mO = *(const ull*)(mz + offO); lO = *(const ull*)(lz + offO); }
        }
        ull vE = pfma(lE, CM1, mE);   // moved - label, even row (2 cols)
        ull vO = pfma(lO, CM1, mO);   // odd row
        float e0, e1, o0, o1;
        upk(vE, e0, e1); upk(vO, o0, o1);
        p0 = pk(e0, o0);              // column L: (even,odd)
        p1 = pk(e1, o1);              // column R: (even,odd)
    };

    auto store = [&](int buf, ull p0, ull p1) {
        if (tid < NSLOT)
            *(ulonglong2*)&tile2[buf][wOff] = make_ulonglong2(p0, p1);
    };

    // ---- packed in-plane partials for this thread's output-row pair ----
    // output col tx (global 32bx+tx) -> raw cols tx+1..tx+3 (local)
    auto compute_pqr = [&](int buf, ull& pP, ull& qP, ull& rP) {
        const ull* b0 = &tile2[buf][ty * TILE_W + tx + 1];
        ull a0 = b0[0],          c0 = b0[1],          e0 = b0[2];
        ull a1 = b0[TILE_W],     c1 = b0[TILE_W + 1], e1 = b0[TILE_W + 2];
        ull s0 = padd(pfma(c0, C2, a0), e0);
        ull d0 = pfma(a0, CM1, e0);
        ull s1 = padd(pfma(c1, C2, a1), e1);
        ull d1 = pfma(a1, CM1, e1);
        qP = pfma(s0, CM1, s1);
        rP = padd(pfma(pmid(s0, s1), C2, s0), s1);
        pP = padd(pfma(pmid(d0, d1), C2, d0), d1);
    };

    float acc = 0.0f;
    ull pP0, qP0, rP0, pP1, qP1, rP1;

    // ---- prologue: planes z0-1, z0, z0+1 into buffers (plane p -> buf p&3) ----
    {
        ull t0, t1;
        fetch(z0 - 1, t0, t1); store((z0 - 1) & 3, t0, t1);
        fetch(z0,     t0, t1); store( z0      & 3, t0, t1);
        fetch(z0 + 1, t0, t1); store((z0 + 1) & 3, t0, t1);
    }
    __syncthreads();

    compute_pqr((z0 - 1) & 3, pP0, qP0, rP0);   // plane z0-1
    compute_pqr( z0      & 3, pP1, qP1, rP1);   // plane z0

    fetch(z0 + 2, preA0, preA1);   // consumed (stored) at k=1
    fetch(z0 + 3, preB0, preB1);   // consumed at k=2

    // ---- main loop: k = 1..ZCHUNK, manually unrolled by 2 (A/B prefetch sets)
    // iter k (z = z0+k): barrier; store plane z+1 (fetched 2 iters ago);
    //   fetch plane z+3; compute pqr(plane z); emit output plane z-1.
    // store plane z+1 -> buf (z+1)&3 overwrites plane z-3 (3 barriers stale). Safe.
    #define EMIT()                                                         \
        do {                                                               \
            ull Gx = padd(pfma(pP1, C2, pP0), pP2);                        \
            ull Gy = padd(pfma(qP1, C2, qP0), qP2);                        \
            ull Gz = pfma(rP0, CM1, rP2);                                  \
            float gxa, gxb, gya, gyb, gza, gzb;                            \
            upk(Gx, gxa, gxb); upk(Gy, gya, gyb); upk(Gz, gza, gzb);       \
            acc += fabsf(gxa) + fabsf(gya);                                \
            acc += fabsf(gza) + fabsf(gxb);                                \
            acc += fabsf(gyb) + fabsf(gzb);                                \
            pP0 = pP1; pP1 = pP2;                                          \
            qP0 = qP1; qP1 = qP2;                                          \
            rP0 = rP1; rP1 = rP2;                                          \
        } while (0)

    #pragma unroll 2
    for (int k = 1; k <= ZCHUNK; k += 2) {
        // ---- iter k (odd): set A ----
        {
            const int z = z0 + k;
            __syncthreads();
            store((z + 1) & 3, preA0, preA1);            // plane z+1 (k<=31 always here)
            if (k + 3 <= ZCHUNK) fetch(z + 3, preA0, preA1);
            ull pP2, qP2, rP2;
            compute_pqr(z & 3, pP2, qP2, rP2);           // plane z
            EMIT();
        }
        // ---- iter k+1 (even): set B ----
        {
            const int z = z0 + k + 1;
            __syncthreads();
            if (k + 1 <= ZCHUNK - 1) store((z + 1) & 3, preB0, preB1);
            if (k + 4 <= ZCHUNK) fetch(z + 3, preB0, preB1);
            ull pP2, qP2, rP2;
            compute_pqr(z & 3, pP2, qP2, rP2);           // plane z
            EMIT();
        }
    }
    #undef EMIT

    // ---- block reduction ----
    #pragma unroll
    for (int o = 16; o > 0; o >>= 1)
        acc += __shfl_down_sync(0xFFFFFFFFu, acc, o);

    __shared__ float wsum[NT / 32];
    if ((tid & 31) == 0) wsum[tid >> 5] = acc;
    __syncthreads();

    if (tid < (NT / 32)) {
        float v = wsum[tid];
        #pragma unroll
        for (int o = (NT / 64); o > 0; o >>= 1)
            v += __shfl_down_sync(0xFFu, v, o);
        if (tid == 0) {
            atomicAdd(&g_acc, v);
            __threadfence();
            if (atomicAdd(&g_cnt, 1u) == TOTAL_CTAS - 1) {
                __threadfence();
                *out = g_acc * SCALE;
                g_acc = 0.0f;      // reset for next (graph-replayed) launch
                g_cnt = 0;
            }
        }
    }
}

extern "C" void kernel_launch(void* const* d_in, const int* in_sizes, int n_in,
                              void* d_out, int out_size)
{
    const float* moved = (const float*)d_in[0];
    const float* label = (const float*)d_in[1];
    float* out = (float*)d_out;

    dim3 grid(GRID_X, GRID_Y, NBATCH * NZCH);   // (5, 12, 10) = 600 CTAs
    dim3 block(TX, TY);                         // (32, 8)
    sobel_loss_kernel<<<grid, block>>>(moved, label, out);
}

// round 9
// speedup vs baseline: 1.1631x; 1.0834x over previous
#include <cuda_runtime.h>

// SobelLoss: loss = sum_{voxels,d in {x,y,z}} |conv_d(moved - label)| / (3*N)
// Shapes: (B=2, 1, D=160, H=192, W=160) fp32, zero padding.
// Sobel separable: S=[1,2,1] smooth, D=[-1,0,1] derivative.
// This version: 128-thread CTAs (8 independent barrier domains / SM),
// ZCHUNK=32, 4 smem buffers, two-plane register prefetch (A/B sets),
// 36-wide 8B-aligned tile, packed f32x2 math on (even,odd) row pairs.

typedef unsigned long long ull;

#define DIMX 160
#define DIMY 192
#define DIMZ 160
#define NBATCH 2
#define PLANE (DIMY * DIMX)

#define TX 32
#define TY 4
#define NT (TX * TY)            // 128
#define OY 8                    // output rows per block (2 per thread)
#define ZCHUNK 32
#define NZCH (DIMZ / ZCHUNK)    // 5

#define TILE_W 36               // raw cols: gx in [32bx-2, 32bx+33] (8B aligned)
#define NPAIR 5                 // 10 raw rows as 5 (even,odd) pairs
#define PLANE_ULL (NPAIR * TILE_W)     // 180 ull per plane buffer
#define NSLOT (NPAIR * (TILE_W / 2))   // 90 fetch slots (col pairs)
#define NBUF 4

#define GRID_X (DIMX / TX)      // 5
#define GRID_Y (DIMY / OY)      // 24
#define TOTAL_CTAS (GRID_X * GRID_Y * NBATCH * NZCH)   // 1200

// 1 / (3 * B*D*H*W) = 1 / 29491200
#define SCALE 3.3908420632258286e-08f

__device__ float    g_acc = 0.0f;
__device__ unsigned g_cnt = 0;

// ---- packed f32x2 helpers (Blackwell sm_103a) ----
__device__ __forceinline__ ull pk(float lo, float hi) {
    ull r; asm("mov.b64 %0, {%1, %2};" : "=l"(r) : "f"(lo), "f"(hi)); return r;
}
__device__ __forceinline__ void upk(ull p, float& lo, float& hi) {
    asm("mov.b64 {%0, %1}, %2;" : "=f"(lo), "=f"(hi) : "l"(p));
}
__device__ __forceinline__ ull padd(ull a, ull b) {
    ull r; asm("add.rn.f32x2 %0, %1, %2;" : "=l"(r) : "l"(a), "l"(b)); return r;
}
__device__ __forceinline__ ull pfma(ull a, ull b, ull c) {   // a*b + c
    ull r; asm("fma.rn.f32x2 %0, %1, %2, %3;" : "=l"(r) : "l"(a), "l"(b), "l"(c)); return r;
}
// (hi(a), lo(b))
__device__ __forceinline__ ull pmid(ull a, ull b) {
    float alo, ahi, blo, bhi;
    upk(a, alo, ahi); upk(b, blo, bhi);
    return pk(ahi, blo);
}

__launch_bounds__(NT, 8)   // force <=64 regs -> 8 CTAs/SM -> 1200 grid ~ ONE wave
__global__ void sobel_loss_kernel(const float* __restrict__ moved,
                                  const float* __restrict__ label,
                                  float* __restrict__ out)
{
    // plane buffer: [pair][col] = float2{ raw row 2*pair, raw row 2*pair+1 }
    __shared__ __align__(16) ull tile2[NBUF][PLANE_ULL];

    const int tx  = threadIdx.x;
    const int ty  = threadIdx.y;
    const int tid = ty * TX + tx;

    const int b  = blockIdx.z / NZCH;
    const int z0 = (blockIdx.z % NZCH) * ZCHUNK;

    const int gy0  = blockIdx.y * OY - 1;     // global y of tile row 0
    const int gxv0 = blockIdx.x * TX - 2;     // global x of tile col 0 (even -> 8B aligned)

    const float* mb = moved + (size_t)b * DIMZ * PLANE;
    const float* lb = label + (size_t)b * DIMZ * PLANE;

    const ull C2  = pk(2.0f, 2.0f);
    const ull CM1 = pk(-1.0f, -1.0f);

    // ---- fetch slot: (row pair, col pair) -> 2 rows x 2 cols per thread ----
    const int pair = tid / (TILE_W / 2);        // 0..4 (tid < 90)
    const int vc2  = tid - pair * (TILE_W / 2); // 0..17
    const int gx   = gxv0 + 2 * vc2;            // even, 8B aligned; pair fully in/out
    const int gyE  = gy0 + 2 * pair;
    const bool slotok = (tid < NSLOT) && ((unsigned)gx < (unsigned)DIMX);
    const int offE = (slotok && (unsigned)gyE       < (unsigned)DIMY) ? (gyE * DIMX + gx)       : -1;
    const int offO = (slotok && (unsigned)(gyE + 1) < (unsigned)DIMY) ? ((gyE + 1) * DIMX + gx) : -1;
    const int wOff = pair * TILE_W + 2 * vc2;   // ull index; 16B aligned (even)

    // two prefetch register sets (A/B) -> 2 planes in flight
    ull preA0, preA1, preB0, preB1;

    auto fetch = [&](int z, ull& p0, ull& p1) {
        ull mE = 0, lE = 0, mO = 0, lO = 0;
        if ((unsigned)z < (unsigned)DIMZ) {
            const float* mz = mb + (size_t)z * PLANE;
            const float* lz = lb + (size_t)z * PLANE;
            if (offE >= 0) { mE = *(const ull*)(mz + offE); lE = *(const ull*)(lz + offE); }
            if (offO >= 0) { mO = *(const ull*)(mz + offO); lO = *(const ull*)(lz + offO); }
        }
        ull vE = pfma(lE, CM1, mE);   // moved - label, even row (2 cols)
        ull vO = pfma(lO, CM1, mO);   // odd row
        float e0, e1, o0, o1;
        upk(vE, e0, e1); upk(vO, o0, o1);
        p0 = pk(e0, o0);              // column L: (even,odd)
        p1 = pk(e1, o1);              // column R: (even,odd)
    };

    auto store = [&](int buf, ull p0, ull p1) {
        if (tid < NSLOT)
            *(ulonglong2*)&tile2[buf][wOff] = make_ulonglong2(p0, p1);
    };

    // ---- packed in-plane partials for this thread's output-row pair ----
    // output col tx (global 32bx+tx) -> raw cols tx+1..tx+3 (local)
    auto compute_pqr = [&](int buf, ull& pP, ull& qP, ull& rP) {
        const ull* b0 = &tile2[buf][ty * TILE_W + tx + 1];
        ull a0 = b0[0],          c0 = b0[1],          e0 = b0[2];
        ull a1 = b0[TILE_W],     c1 = b0[TILE_W + 1], e1 = b0[TILE_W + 2];
        ull s0 = padd(pfma(c0, C2, a0), e0);
        ull d0 = pfma(a0, CM1, e0);
        ull s1 = padd(pfma(c1, C2, a1), e1);
        ull d1 = pfma(a1, CM1, e1);
        qP = pfma(s0, CM1, s1);
        rP = padd(pfma(pmid(s0, s1), C2, s0), s1);
        pP = padd(pfma(pmid(d0, d1), C2, d0), d1);
    };

    float acc = 0.0f;
    ull pP0, qP0, rP0, pP1, qP1, rP1;

    // ---- prologue: planes z0-1, z0, z0+1 into buffers (plane p -> buf p&3) ----
    {
        ull t0, t1;
        fetch(z0 - 1, t0, t1); store((z0 - 1) & 3, t0, t1);
        fetch(z0,     t0, t1); store( z0      & 3, t0, t1);
        fetch(z0 + 1, t0, t1); store((z0 + 1) & 3, t0, t1);
    }
    __syncthreads();

    compute_pqr((z0 - 1) & 3, pP0, qP0, rP0);   // plane z0-1
    compute_pqr( z0      & 3, pP1, qP1, rP1);   // plane z0

    fetch(z0 + 2, preA0, preA1);   // consumed (stored) at k=1
    fetch(z0 + 3, preB0, preB1);   // consumed at k=2

    // ---- main loop: k = 1..ZCHUNK, manually unrolled by 2 (A/B prefetch sets)
    // iter k (z = z0+k): barrier; store plane z+1 (fetched 2 iters ago);
    //   fetch plane z+3; compute pqr(plane z); emit output plane z-1.
    // store plane z+1 -> buf (z+1)&3 overwrites plane z-3 (3 barriers stale). Safe.
    #define EMIT()                                                         \
        do {                                                               \
            ull Gx = padd(pfma(pP1, C2, pP0), pP2);                        \
            ull Gy = padd(pfma(qP1, C2, qP0), qP2);                        \
            ull Gz = pfma(rP0, CM1, rP2);                                  \
            float gxa, gxb, gya, gyb, gza, gzb;                            \
            upk(Gx, gxa, gxb); upk(Gy, gya, gyb); upk(Gz, gza, gzb);       \
            acc += fabsf(gxa) + fabsf(gya);                                \
            acc += fabsf(gza) + fabsf(gxb);                                \
            acc += fabsf(gyb) + fabsf(gzb);                                \
            pP0 = pP1; pP1 = pP2;                                          \
            qP0 = qP1; qP1 = qP2;                                          \
            rP0 = rP1; rP1 = rP2;                                          \
        } while (0)

    #pragma unroll 2
    for (int k = 1; k <= ZCHUNK; k += 2) {
        // ---- iter k (odd): set A ----
        {
            const int z = z0 + k;
            __syncthreads();
            store((z + 1) & 3, preA0, preA1);            // plane z+1
            if (k + 3 <= ZCHUNK) fetch(z + 3, preA0, preA1);
            ull pP2, qP2, rP2;
            compute_pqr(z & 3, pP2, qP2, rP2);           // plane z
            EMIT();
        }
        // ---- iter k+1 (even): set B ----
        {
            const int z = z0 + k + 1;
            __syncthreads();
            if (k + 1 <= ZCHUNK - 1) store((z + 1) & 3, preB0, preB1);
            if (k + 4 <= ZCHUNK) fetch(z + 3, preB0, preB1);
            ull pP2, qP2, rP2;
            compute_pqr(z & 3, pP2, qP2, rP2);           // plane z
            EMIT();
        }
    }
    #undef EMIT

    // ---- block reduction ----
    #pragma unroll
    for (int o = 16; o > 0; o >>= 1)
        acc += __shfl_down_sync(0xFFFFFFFFu, acc, o);

    __shared__ float wsum[NT / 32];
    if ((tid & 31) == 0) wsum[tid >> 5] = acc;
    __syncthreads();

    if (tid < (NT / 32)) {
        float v = wsum[tid];
        #pragma unroll
        for (int o = (NT / 64); o > 0; o >>= 1)
            v += __shfl_down_sync(0xFFu, v, o);
        if (tid == 0) {
            atomicAdd(&g_acc, v);
            __threadfence();
            if (atomicAdd(&g_cnt, 1u) == TOTAL_CTAS - 1) {
                __threadfence();
                *out = g_acc * SCALE;
                g_acc = 0.0f;      // reset for next (graph-replayed) launch
                g_cnt = 0;
            }
        }
    }
}

extern "C" void kernel_launch(void* const* d_in, const int* in_sizes, int n_in,
                              void* d_out, int out_size)
{
    const float* moved = (const float*)d_in[0];
    const float* label = (const float*)d_in[1];
    float* out = (float*)d_out;

    dim3 grid(GRID_X, GRID_Y, NBATCH * NZCH);   // (5, 24, 10) = 1200 CTAs
    dim3 block(TX, TY);                         // (32, 4)
    sobel_loss_kernel<<<grid, block>>>(moved, label, out);
}